// round 16
// baseline (speedup 1.0000x reference)
#include <cuda_runtime.h>
#include <cuda_bf16.h>

// Shapes (fixed): B=32, D=64, N=254, L=16, H=128, P=96
#define NB 32
#define ND 64
#define NN 254
#define NL 16
#define NH 128
#define NP 96
#define PAIRS (NB*ND)          // 2048
#define XPP (NN*NL)            // 4064 floats per (b,d) pair
#define OUT_T_ELEMS (NB*NP*ND) // 196608
#define NPRE 38                // producer blocks

// ---- shared precomputed tensors (tiny) ----
__device__ __align__(16) float g_constvec[NH];
__device__ __align__(16) float g_M[NN*NL];   // M[n,l] = pos[n,:] . W_enc[l,:]
__device__ __align__(16) float g_D2[NN];     // pos[n,:] . constvec
__device__ __align__(16) float g_G[NL*NL];   // G[l',l] = W_enc[l',:] . W_enc[l,:]
__device__ __align__(16) float g_u[NL];      // W_enc[l,:] . constvec
__device__ __align__(16) float g_wb[NL];     // W_enc[l,:] . b_enc
__device__ __align__(16) float g_s0pad[4];   // [0] = b_enc . constvec
__device__ int g_flag1;                       // constvec ready (monotone across replays)
__device__ int g_done;                        // precompute producers done (monotone)

__device__ __forceinline__ int ld_acq(const int* p) {
    int v;
    asm volatile("ld.acquire.gpu.global.b32 %0, [%1];" : "=r"(v) : "l"(p));
    return v;
}

// vectorized length-128 dot with 4 accumulators
__device__ __forceinline__ float dot128(const float4* __restrict__ a,
                                        const float4* __restrict__ b) {
    float s0=0.f, s1=0.f, s2=0.f, s3=0.f;
    #pragma unroll
    for (int i = 0; i < 32; i += 4) {
        float4 a0=a[i],   b0=b[i];
        float4 a1=a[i+1], b1=b[i+1];
        float4 a2=a[i+2], b2=b[i+2];
        float4 a3=a[i+3], b3=b[i+3];
        s0 += a0.x*b0.x + a0.y*b0.y + a0.z*b0.z + a0.w*b0.w;
        s1 += a1.x*b1.x + a1.y*b1.y + a1.z*b1.z + a1.w*b1.w;
        s2 += a2.x*b2.x + a2.y*b2.y + a2.z*b2.z + a2.w*b2.w;
        s3 += a3.x*b3.x + a3.y*b3.y + a3.z*b3.z + a3.w*b3.w;
    }
    return (s0+s1)+(s2+s3);
}

__global__ __launch_bounds__(128, 4)
void k_all(const float* __restrict__ x, float* __restrict__ x_copy,
           const float* __restrict__ W_enc, const float* __restrict__ b_enc,
           const float* __restrict__ pos,
           const float* __restrict__ W1, const float* __restrict__ b1,
           const float* __restrict__ W2, const float* __restrict__ b2,
           float* __restrict__ out_t) {
    __shared__ __align__(16) float4 xsS4[4][4];       // [warp] xsum quarters
    __shared__ __align__(16) float4 poS4[4][4];       // [pair] pooled quarters (unnorm)
    __shared__ float wsumS[4];                        // [pair] sum|score|
    __shared__ __align__(16) float  hdnT[NH*4];       // [h][pair-in-block]
    __shared__ __align__(16) float4 red7[4][4][24];   // [warp][pair][p-float4]

    const int tid  = threadIdx.x;
    const int pid  = blockIdx.x;
    const int lane = tid & 31;
    const int wrp  = tid >> 5;
    const int q    = lane & 3;         // l-quarter index
    const int r    = lane >> 2;        // row-within-8 index
    const float4* __restrict__ pos4 = (const float4*)pos;
    const float4* __restrict__ W4   = (const float4*)W_enc;

    // ---------- inline precompute (first NPRE blocks; unchanged) ----------
    if (pid < NPRE) {
        if (pid == 0) {
            float a0=0.f, a1=0.f, a2=0.f, a3=0.f;
            #pragma unroll 2
            for (int n = 0; n < 252; n += 4) {
                a0 += __ldg(pos + (n+0)*NH + tid);
                a1 += __ldg(pos + (n+1)*NH + tid);
                a2 += __ldg(pos + (n+2)*NH + tid);
                a3 += __ldg(pos + (n+3)*NH + tid);
            }
            a0 += __ldg(pos + 252*NH + tid);
            a1 += __ldg(pos + 253*NH + tid);
            g_constvec[tid] = (float)NN * b_enc[tid] + ((a0+a1)+(a2+a3));
            __threadfence();
            __syncthreads();
            if (tid == 0) atomicAdd(&g_flag1, 1);
        } else if (pid <= 34) {
            int j = (pid-1)*128 + tid;
            if (j < NN*NL) {                         // M
                g_M[j] = dot128(pos4 + (j>>4)*32, W4 + (j&15)*32);
            } else if (j < NN*NL + NL*NL) {          // G
                int k = j - NN*NL;
                g_G[k] = dot128(W4 + (k>>4)*32, W4 + (k&15)*32);
            }
        } else {
            if (tid == 0) { while (ld_acq(&g_flag1) == 0) {} }
            __syncthreads();
            const float4* cv4 = (const float4*)g_constvec;
            int j = (pid-35)*128 + tid;
            if (j < NN) {                            // D2
                g_D2[j] = dot128(pos4 + j*32, cv4);
            } else if (j < NN + NL) {                // u
                g_u[j-NN] = dot128(W4 + (j-NN)*32, cv4);
            } else if (j < NN + 2*NL) {              // wb
                g_wb[j-NN-NL] = dot128(W4 + (j-NN-NL)*32, (const float4*)b_enc);
            } else if (j == NN + 2*NL) {             // s0
                g_s0pad[0] = dot128((const float4*)b_enc, cv4);
            }
        }
        __threadfence();
        __syncthreads();
        if (tid == 0) atomicAdd(&g_done, 1);
    }

    // ---------- warp-per-pair main path ----------
    const int pair = pid*4 + wrp;
    const float4* __restrict__ xp4 = (const float4*)(x + (size_t)pair * XPP);
    float4* __restrict__ xc4 = (float4*)(x_copy + (size_t)pair * XPP);

    // Pass 1: stream x (cached) + passthrough copy + xsum partials (peeled tail)
    float ls0=0.f, ls1=0.f, ls2=0.f, ls3=0.f;
    #pragma unroll 8
    for (int j = 0; j < 31; j++) {
        int i = j*32 + lane;
        float4 f = xp4[i];
        __stcs(xc4 + i, f);
        ls0 += f.x; ls1 += f.y; ls2 += f.z; ls3 += f.w;
    }
    if (lane < 24) {                    // i = 992+lane < 1016
        int i = 992 + lane;
        float4 f = xp4[i];
        __stcs(xc4 + i, f);
        ls0 += f.x; ls1 += f.y; ls2 += f.z; ls3 += f.w;
    }
    #pragma unroll
    for (int m = 4; m <= 16; m <<= 1) {
        ls0 += __shfl_xor_sync(0xffffffffu, ls0, m);
        ls1 += __shfl_xor_sync(0xffffffffu, ls1, m);
        ls2 += __shfl_xor_sync(0xffffffffu, ls2, m);
        ls3 += __shfl_xor_sync(0xffffffffu, ls3, m);
    }
    float4 xsq = make_float4(ls0, ls1, ls2, ls3);   // own quarter q of xsum
    if (lane < 4) xsS4[wrp][lane] = xsq;            // quarter a from lane a
    __syncwarp();

    // wait for precompute (first pairs only; nearly-free afterwards)
    while (ld_acq(&g_done) < NPRE) {}

    // v (own quarter) = u_q + sum_l' xsum[l'] * G[l'][quarter q]  (xsum from smem)
    const float* __restrict__ xsP = (const float*)&xsS4[wrp];
    const float4* __restrict__ G4 = (const float4*)g_G;
    float4 vq = __ldg(&((const float4*)g_u)[q]);
    #pragma unroll
    for (int lp = 0; lp < 16; lp++) {
        float xl = xsP[lp];                          // LDS broadcast
        float4 g = __ldg(&G4[lp*4 + q]);
        vq.x += xl*g.x; vq.y += xl*g.y; vq.z += xl*g.z; vq.w += xl*g.w;
    }
    // sS = s0 + xsum . wb
    float sS = __ldg(&g_s0pad[0]);
    {
        const float4* __restrict__ wb4 = (const float4*)g_wb;
        #pragma unroll
        for (int a = 0; a < 4; a++) {
            float4 xa = xsS4[wrp][a];                // LDS.128 broadcast
            float4 w  = __ldg(&wb4[a]);
            sS += xa.x*w.x + xa.y*w.y + xa.z*w.z + xa.w*w.w;
        }
    }

    // Pass 2: fused score + pool (x re-read, L1-hot; peeled tail)
    const float4* __restrict__ M4 = (const float4*)g_M;
    float p0=0.f, p1=0.f, p2=0.f, p3=0.f, myabs=0.f;
    #pragma unroll 8
    for (int j = 0; j < 31; j++) {
        int i = j*32 + lane;
        int n = j*8 + r;                             // n <= 247 < 254
        float4 f  = xp4[i];
        float4 m  = __ldg(&M4[n*4 + q]);
        float  d2 = __ldg(g_D2 + n);
        float part = f.x*vq.x + f.y*vq.y + f.z*vq.z + f.w*vq.w
                   + xsq.x*m.x + xsq.y*m.y + xsq.z*m.z + xsq.w*m.w;
        part += __shfl_xor_sync(0xffffffffu, part, 1);
        part += __shfl_xor_sync(0xffffffffu, part, 2);
        float a = part + sS + d2;
        p0 += f.x*a; p1 += f.y*a; p2 += f.z*a; p3 += f.w*a;
        if (q == 0) myabs += fabsf(a);
    }
    {   // j = 31: n = 248 + r valid iff lane < 24
        int i = 992 + lane;
        int n = 248 + r;
        float4 f = make_float4(0.f,0.f,0.f,0.f);
        float4 m = make_float4(0.f,0.f,0.f,0.f);
        float d2 = 0.f;
        if (lane < 24) {
            f  = xp4[i];
            m  = __ldg(&M4[n*4 + q]);
            d2 = __ldg(g_D2 + n);
        }
        float part = f.x*vq.x + f.y*vq.y + f.z*vq.z + f.w*vq.w
                   + xsq.x*m.x + xsq.y*m.y + xsq.z*m.z + xsq.w*m.w;
        part += __shfl_xor_sync(0xffffffffu, part, 1);
        part += __shfl_xor_sync(0xffffffffu, part, 2);
        float a = part + sS + d2;
        if (lane < 24) {
            p0 += f.x*a; p1 += f.y*a; p2 += f.z*a; p3 += f.w*a;
            if (q == 0) myabs += fabsf(a);
        }
    }
    #pragma unroll
    for (int m = 4; m <= 16; m <<= 1) {
        p0 += __shfl_xor_sync(0xffffffffu, p0, m);
        p1 += __shfl_xor_sync(0xffffffffu, p1, m);
        p2 += __shfl_xor_sync(0xffffffffu, p2, m);
        p3 += __shfl_xor_sync(0xffffffffu, p3, m);
        myabs += __shfl_xor_sync(0xffffffffu, myabs, m);
    }
    if (lane < 4) poS4[wrp][lane] = make_float4(p0, p1, p2, p3);
    if (lane == 0) wsumS[wrp] = myabs;
    __syncthreads();                                   // SYNC 1: poS/wsumS ready

    // Cooperative hidden: tid = h; one W1 column load serves all 4 pairs.
    {
        const float* __restrict__ poP = (const float*)poS4;   // [pair][16]
        float a0=0.f, a1=0.f, a2=0.f, a3=0.f;
        #pragma unroll
        for (int l = 0; l < 16; l++) {
            float wl = __ldg(W1 + l*NH + tid);
            a0 += poP[ 0+l]*wl;
            a1 += poP[16+l]*wl;
            a2 += poP[32+l]*wl;
            a3 += poP[48+l]*wl;
        }
        float bb = __ldg(b1 + tid);
        float4 hv;
        float t;
        t = bb + a0 * (1.0f/wsumS[0]); hv.x = t > 0.f ? t : 0.2f*t;
        t = bb + a1 * (1.0f/wsumS[1]); hv.y = t > 0.f ? t : 0.2f*t;
        t = bb + a2 * (1.0f/wsumS[2]); hv.z = t > 0.f ? t : 0.2f*t;
        t = bb + a3 * (1.0f/wsumS[3]); hv.w = t > 0.f ? t : 0.2f*t;
        ((float4*)hdnT)[tid] = hv;                     // [h] -> (p0,p1,p2,p3)
    }
    __syncthreads();                                   // SYNC 2: hdnT ready

    // W2 block phase: warp w covers hh in [32w, 32w+32); one W2 row serves 4 pairs.
    const float4* __restrict__ W24 = (const float4*)W2;    // [h][24] float4
    const float4* __restrict__ hT4 = (const float4*)hdnT;  // [h] -> (p0,p1,p2,p3)
    float4 a0 = make_float4(0.f,0.f,0.f,0.f);
    float4 a1 = make_float4(0.f,0.f,0.f,0.f);
    float4 a2 = make_float4(0.f,0.f,0.f,0.f);
    float4 a3 = make_float4(0.f,0.f,0.f,0.f);
    #pragma unroll 4
    for (int t = 0; t < 32; t++) {
        int hh = wrp*32 + t;
        float4 hv = hT4[hh];            // LDS.128 broadcast
        if (lane < 24) {
            float4 w4 = __ldg(&W24[hh*24 + lane]);
            a0.x += hv.x*w4.x; a0.y += hv.x*w4.y; a0.z += hv.x*w4.z; a0.w += hv.x*w4.w;
            a1.x += hv.y*w4.x; a1.y += hv.y*w4.y; a1.z += hv.y*w4.z; a1.w += hv.y*w4.w;
            a2.x += hv.z*w4.x; a2.y += hv.z*w4.y; a2.z += hv.z*w4.z; a2.w += hv.z*w4.w;
            a3.x += hv.w*w4.x; a3.y += hv.w*w4.y; a3.z += hv.w*w4.z; a3.w += hv.w*w4.w;
        }
    }
    if (lane < 24) {
        red7[wrp][0][lane] = a0;
        red7[wrp][1][lane] = a1;
        red7[wrp][2][lane] = a2;
        red7[wrp][3][lane] = a3;
    }
    __syncthreads();                                   // SYNC 3: partials ready

    // warp wrp finalizes its own pair's output
    if (lane < 24) {
        float4 t0 = red7[0][wrp][lane];
        float4 t1 = red7[1][wrp][lane];
        float4 t2 = red7[2][wrp][lane];
        float4 t3 = red7[3][wrp][lane];
        float4 bb = __ldg(&((const float4*)b2)[lane]);
        int b = pair >> 6, d = pair & 63;
        float* dst = out_t + b*(NP*ND) + d;
        int p = lane*4;
        dst[(p+0)*ND] = (t0.x + t1.x) + (t2.x + t3.x) + bb.x;
        dst[(p+1)*ND] = (t0.y + t1.y) + (t2.y + t3.y) + bb.y;
        dst[(p+2)*ND] = (t0.z + t1.z) + (t2.z + t3.z) + bb.z;
        dst[(p+3)*ND] = (t0.w + t1.w) + (t2.w + t3.w) + bb.w;
    }
}

extern "C" void kernel_launch(void* const* d_in, const int* in_sizes, int n_in,
                              void* d_out, int out_size) {
    const float* x     = (const float*)d_in[0];
    const float* W_enc = (const float*)d_in[1];
    const float* b_enc = (const float*)d_in[2];
    const float* W1    = (const float*)d_in[3];
    const float* b1    = (const float*)d_in[4];
    const float* W2    = (const float*)d_in[5];
    const float* b2    = (const float*)d_in[6];
    const float* pos   = (const float*)d_in[7];

    float* out   = (float*)d_out;          // (B,P,D) first
    float* xcopy = out + OUT_T_ELEMS;      // then p = x passthrough

    k_all<<<PAIRS/4, 128>>>(x, xcopy, W_enc, b_enc, pos, W1, b1, W2, b2, out);
}

// round 17
// speedup vs baseline: 1.0208x; 1.0208x over previous
#include <cuda_runtime.h>
#include <cuda_bf16.h>

// Shapes (fixed): B=32, D=64, N=254, L=16, H=128, P=96
#define NB 32
#define ND 64
#define NN 254
#define NL 16
#define NH 128
#define NP 96
#define PAIRS (NB*ND)          // 2048
#define XPP (NN*NL)            // 4064 floats per (b,d) pair
#define OUT_T_ELEMS (NB*NP*ND) // 196608
#define NPRE 38                // producer blocks

typedef unsigned long long u64;

// ---- packed f32x2 helpers (Blackwell: 2 fp32 ops per instruction) ----
__device__ __forceinline__ u64 fma2(u64 a, u64 b, u64 c) {
    u64 d; asm("fma.rn.f32x2 %0, %1, %2, %3;" : "=l"(d) : "l"(a), "l"(b), "l"(c)); return d;
}
__device__ __forceinline__ u64 mul2(u64 a, u64 b) {
    u64 d; asm("mul.rn.f32x2 %0, %1, %2;" : "=l"(d) : "l"(a), "l"(b)); return d;
}
__device__ __forceinline__ u64 add2(u64 a, u64 b) {
    u64 d; asm("add.rn.f32x2 %0, %1, %2;" : "=l"(d) : "l"(a), "l"(b)); return d;
}
__device__ __forceinline__ u64 pack2(float lo, float hi) {
    u64 d; asm("mov.b64 %0, {%1, %2};" : "=l"(d) : "f"(lo), "f"(hi)); return d;
}
__device__ __forceinline__ void unpack2(u64 d, float& lo, float& hi) {
    asm("mov.b64 {%0, %1}, %2;" : "=f"(lo), "=f"(hi) : "l"(d));
}

// ---- shared precomputed tensors (tiny) ----
__device__ __align__(16) float g_constvec[NH];
__device__ __align__(16) float g_M[NN*NL];   // M[n,l] = pos[n,:] . W_enc[l,:]
__device__ __align__(16) float g_D2[NN];     // pos[n,:] . constvec
__device__ __align__(16) float g_G[NL*NL];   // G[l',l] = W_enc[l',:] . W_enc[l,:]
__device__ __align__(16) float g_u[NL];      // W_enc[l,:] . constvec
__device__ __align__(16) float g_wb[NL];     // W_enc[l,:] . b_enc
__device__ __align__(16) float g_s0pad[4];   // [0] = b_enc . constvec
__device__ int g_flag1;                       // constvec ready (monotone across replays)
__device__ int g_done;                        // precompute producers done (monotone)

__device__ __forceinline__ int ld_acq(const int* p) {
    int v;
    asm volatile("ld.acquire.gpu.global.b32 %0, [%1];" : "=r"(v) : "l"(p));
    return v;
}

// vectorized length-128 dot with 4 accumulators
__device__ __forceinline__ float dot128(const float4* __restrict__ a,
                                        const float4* __restrict__ b) {
    float s0=0.f, s1=0.f, s2=0.f, s3=0.f;
    #pragma unroll
    for (int i = 0; i < 32; i += 4) {
        float4 a0=a[i],   b0=b[i];
        float4 a1=a[i+1], b1=b[i+1];
        float4 a2=a[i+2], b2=b[i+2];
        float4 a3=a[i+3], b3=b[i+3];
        s0 += a0.x*b0.x + a0.y*b0.y + a0.z*b0.z + a0.w*b0.w;
        s1 += a1.x*b1.x + a1.y*b1.y + a1.z*b1.z + a1.w*b1.w;
        s2 += a2.x*b2.x + a2.y*b2.y + a2.z*b2.z + a2.w*b2.w;
        s3 += a3.x*b3.x + a3.y*b3.y + a3.z*b3.z + a3.w*b3.w;
    }
    return (s0+s1)+(s2+s3);
}

__global__ __launch_bounds__(128, 4)
void k_all(const float* __restrict__ x, float* __restrict__ x_copy,
           const float* __restrict__ W_enc, const float* __restrict__ b_enc,
           const float* __restrict__ pos,
           const float* __restrict__ W1, const float* __restrict__ b1,
           const float* __restrict__ W2, const float* __restrict__ b2,
           float* __restrict__ out_t) {
    __shared__ __align__(16) float  hdnT[NH*4];       // [h][pair-in-block]
    __shared__ __align__(16) float4 red7[4][4][24];   // [warp][pair][p-float4]

    const int tid  = threadIdx.x;
    const int pid  = blockIdx.x;
    const int lane = tid & 31;
    const int wrp  = tid >> 5;
    const int q    = lane & 3;         // l-quarter index
    const int r    = lane >> 2;        // row-within-8 index
    const float4* __restrict__ pos4 = (const float4*)pos;
    const float4* __restrict__ W4   = (const float4*)W_enc;

    // ---------- inline precompute (first NPRE blocks; unchanged) ----------
    if (pid < NPRE) {
        if (pid == 0) {
            float a0=0.f, a1=0.f, a2=0.f, a3=0.f;
            #pragma unroll 2
            for (int n = 0; n < 252; n += 4) {
                a0 += __ldg(pos + (n+0)*NH + tid);
                a1 += __ldg(pos + (n+1)*NH + tid);
                a2 += __ldg(pos + (n+2)*NH + tid);
                a3 += __ldg(pos + (n+3)*NH + tid);
            }
            a0 += __ldg(pos + 252*NH + tid);
            a1 += __ldg(pos + 253*NH + tid);
            g_constvec[tid] = (float)NN * b_enc[tid] + ((a0+a1)+(a2+a3));
            __threadfence();
            __syncthreads();
            if (tid == 0) atomicAdd(&g_flag1, 1);
        } else if (pid <= 34) {
            int j = (pid-1)*128 + tid;
            if (j < NN*NL) {                         // M
                g_M[j] = dot128(pos4 + (j>>4)*32, W4 + (j&15)*32);
            } else if (j < NN*NL + NL*NL) {          // G
                int k = j - NN*NL;
                g_G[k] = dot128(W4 + (k>>4)*32, W4 + (k&15)*32);
            }
        } else {
            if (tid == 0) { while (ld_acq(&g_flag1) == 0) {} }
            __syncthreads();
            const float4* cv4 = (const float4*)g_constvec;
            int j = (pid-35)*128 + tid;
            if (j < NN) {                            // D2
                g_D2[j] = dot128(pos4 + j*32, cv4);
            } else if (j < NN + NL) {                // u
                g_u[j-NN] = dot128(W4 + (j-NN)*32, cv4);
            } else if (j < NN + 2*NL) {              // wb
                g_wb[j-NN-NL] = dot128(W4 + (j-NN-NL)*32, (const float4*)b_enc);
            } else if (j == NN + 2*NL) {             // s0
                g_s0pad[0] = dot128((const float4*)b_enc, cv4);
            }
        }
        __threadfence();
        __syncthreads();
        if (tid == 0) atomicAdd(&g_done, 1);
    }

    // ---------- warp-per-pair main path ----------
    const int pair = pid*4 + wrp;
    const ulonglong2* __restrict__ xp2 = (const ulonglong2*)(x + (size_t)pair * XPP);
    ulonglong2* __restrict__ xc2 = (ulonglong2*)(x_copy + (size_t)pair * XPP);

    // Pass 1: stream x (cached) + passthrough copy + packed xsum partials.
    u64 s01 = 0ull, s23 = 0ull;          // bit pattern 0 == (0.0f, 0.0f)
    #pragma unroll 8
    for (int j = 0; j < 32; j++) {
        int i = j*32 + lane;
        if (i < XPP/4) {
            ulonglong2 f2 = xp2[i];
            asm volatile("st.global.cs.v2.u64 [%0], {%1,%2};"
                         :: "l"(xc2 + i), "l"(f2.x), "l"(f2.y) : "memory");
            s01 = add2(s01, f2.x);
            s23 = add2(s23, f2.y);
        }
    }
    float ls0, ls1, ls2, ls3;
    unpack2(s01, ls0, ls1);
    unpack2(s23, ls2, ls3);
    #pragma unroll
    for (int m = 4; m <= 16; m <<= 1) {
        ls0 += __shfl_xor_sync(0xffffffffu, ls0, m);
        ls1 += __shfl_xor_sync(0xffffffffu, ls1, m);
        ls2 += __shfl_xor_sync(0xffffffffu, ls2, m);
        ls3 += __shfl_xor_sync(0xffffffffu, ls3, m);
    }

    // wait for precompute (first pairs only; nearly-free afterwards)
    while (ld_acq(&g_done) < NPRE) {}

    // materialize xsum[0..15] per lane
    float xs[16];
    #pragma unroll
    for (int a = 0; a < 4; a++) {
        xs[4*a+0] = __shfl_sync(0xffffffffu, ls0, a);
        xs[4*a+1] = __shfl_sync(0xffffffffu, ls1, a);
        xs[4*a+2] = __shfl_sync(0xffffffffu, ls2, a);
        xs[4*a+3] = __shfl_sync(0xffffffffu, ls3, a);
    }

    // v (own quarter) = u_q + sum_l' xsum[l'] * G[l'][quarter q]
    const float4* __restrict__ G4 = (const float4*)g_G;
    float4 vq = __ldg(&((const float4*)g_u)[q]);
    #pragma unroll
    for (int lp = 0; lp < 16; lp++) {
        float4 g = __ldg(&G4[lp*4 + q]);
        vq.x += xs[lp]*g.x; vq.y += xs[lp]*g.y; vq.z += xs[lp]*g.z; vq.w += xs[lp]*g.w;
    }
    // sS = s0 + xsum . wb   (redundant per lane)
    float sS = __ldg(&g_s0pad[0]);
    {
        const float4* __restrict__ wb4 = (const float4*)g_wb;
        #pragma unroll
        for (int a = 0; a < 4; a++) {
            float4 w = __ldg(&wb4[a]);
            sS += xs[4*a+0]*w.x + xs[4*a+1]*w.y + xs[4*a+2]*w.z + xs[4*a+3]*w.w;
        }
    }

    // packed copies of vq / own xsum quarter
    const u64 vq01 = pack2(vq.x, vq.y), vq23 = pack2(vq.z, vq.w);
    const u64 xq01 = pack2(ls0, ls1),   xq23 = pack2(ls2, ls3);

    // Pass 2: fused score + pool (x re-read, L1-hot), packed math
    const ulonglong2* __restrict__ M2 = (const ulonglong2*)g_M;  // [NN][4] per-quarter
    u64 pp01 = 0ull, pp23 = 0ull;
    float myabs = 0.f;
    #pragma unroll 8
    for (int j = 0; j < 32; j++) {
        int i = j*32 + lane;
        int n = j*8 + r;
        ulonglong2 f2 = make_ulonglong2(0ull, 0ull);
        ulonglong2 m2 = make_ulonglong2(0ull, 0ull);
        float d2 = 0.f;
        if (n < NN) {
            f2 = xp2[i];
            m2 = __ldg(M2 + n*4 + q);
            d2 = __ldg(g_D2 + n);
        }
        u64 t = fma2(f2.x, vq01, fma2(f2.y, vq23, fma2(m2.x, xq01, mul2(m2.y, xq23))));
        float tlo, thi;
        unpack2(t, tlo, thi);
        float part = tlo + thi;
        part += __shfl_xor_sync(0xffffffffu, part, 1);
        part += __shfl_xor_sync(0xffffffffu, part, 2);
        float a = part + sS + d2;
        if (n < NN) {
            u64 ab = pack2(a, a);
            pp01 = fma2(f2.x, ab, pp01);
            pp23 = fma2(f2.y, ab, pp23);
            if (q == 0) myabs += fabsf(a);
        }
    }
    float p0, p1, p2, p3;
    unpack2(pp01, p0, p1);
    unpack2(pp23, p2, p3);
    #pragma unroll
    for (int m = 4; m <= 16; m <<= 1) {
        p0 += __shfl_xor_sync(0xffffffffu, p0, m);
        p1 += __shfl_xor_sync(0xffffffffu, p1, m);
        p2 += __shfl_xor_sync(0xffffffffu, p2, m);
        p3 += __shfl_xor_sync(0xffffffffu, p3, m);
        myabs += __shfl_xor_sync(0xffffffffu, myabs, m);
    }
    float inv = 1.0f / __shfl_sync(0xffffffffu, myabs, 0);

    // materialize pooled[0..15] (unnormalized)
    float po[16];
    #pragma unroll
    for (int a = 0; a < 4; a++) {
        po[4*a+0] = __shfl_sync(0xffffffffu, p0, a);
        po[4*a+1] = __shfl_sync(0xffffffffu, p1, a);
        po[4*a+2] = __shfl_sync(0xffffffffu, p2, a);
        po[4*a+3] = __shfl_sync(0xffffffffu, p3, a);
    }

    // FF hidden: lane owns h = lane + 32k, k=0..3; deposit transposed to smem
    #pragma unroll
    for (int k = 0; k < 4; k++) {
        int h = lane + 32*k;
        float a = 0.f;
        #pragma unroll
        for (int l = 0; l < NL; l++) a += po[l] * __ldg(W1 + l*NH + h);
        a = __ldg(b1 + h) + a * inv;
        hdnT[h*4 + wrp] = (a > 0.f ? a : 0.2f * a);
    }
    __syncthreads();                                   // hdnT ready (all 4 pairs)

    // W2 block phase: warp w covers hh in [32w, 32w+32); one W2 row serves 4 pairs.
    // Packed: 8 FMA2 per iteration instead of 16 FMA.
    const ulonglong2* __restrict__ W22 = (const ulonglong2*)W2;  // [h][24] in 16B units
    const float4* __restrict__ hT4 = (const float4*)hdnT;        // [h] -> (p0,p1,p2,p3)
    u64 a0x=0ull, a0y=0ull, a1x=0ull, a1y=0ull;
    u64 a2x=0ull, a2y=0ull, a3x=0ull, a3y=0ull;
    #pragma unroll 4
    for (int t = 0; t < 32; t++) {
        int hh = wrp*32 + t;
        float4 hv = hT4[hh];            // LDS.128 broadcast
        if (lane < 24) {
            ulonglong2 w2 = __ldg(W22 + hh*24 + lane);
            u64 h0 = pack2(hv.x, hv.x);
            u64 h1 = pack2(hv.y, hv.y);
            u64 h2 = pack2(hv.z, hv.z);
            u64 h3 = pack2(hv.w, hv.w);
            a0x = fma2(h0, w2.x, a0x); a0y = fma2(h0, w2.y, a0y);
            a1x = fma2(h1, w2.x, a1x); a1y = fma2(h1, w2.y, a1y);
            a2x = fma2(h2, w2.x, a2x); a2y = fma2(h2, w2.y, a2y);
            a3x = fma2(h3, w2.x, a3x); a3y = fma2(h3, w2.y, a3y);
        }
    }
    if (lane < 24) {
        float4 a0, a1, a2, a3;
        unpack2(a0x, a0.x, a0.y); unpack2(a0y, a0.z, a0.w);
        unpack2(a1x, a1.x, a1.y); unpack2(a1y, a1.z, a1.w);
        unpack2(a2x, a2.x, a2.y); unpack2(a2y, a2.z, a2.w);
        unpack2(a3x, a3.x, a3.y); unpack2(a3y, a3.z, a3.w);
        red7[wrp][0][lane] = a0;
        red7[wrp][1][lane] = a1;
        red7[wrp][2][lane] = a2;
        red7[wrp][3][lane] = a3;
    }
    __syncthreads();                                   // partials ready

    // warp wrp finalizes its own pair's output
    if (lane < 24) {
        float4 t0 = red7[0][wrp][lane];
        float4 t1 = red7[1][wrp][lane];
        float4 t2 = red7[2][wrp][lane];
        float4 t3 = red7[3][wrp][lane];
        float4 bb = __ldg(&((const float4*)b2)[lane]);
        int b = pair >> 6, d = pair & 63;
        float* dst = out_t + b*(NP*ND) + d;
        int p = lane*4;
        dst[(p+0)*ND] = (t0.x + t1.x) + (t2.x + t3.x) + bb.x;
        dst[(p+1)*ND] = (t0.y + t1.y) + (t2.y + t3.y) + bb.y;
        dst[(p+2)*ND] = (t0.z + t1.z) + (t2.z + t3.z) + bb.z;
        dst[(p+3)*ND] = (t0.w + t1.w) + (t2.w + t3.w) + bb.w;
    }
}

extern "C" void kernel_launch(void* const* d_in, const int* in_sizes, int n_in,
                              void* d_out, int out_size) {
    const float* x     = (const float*)d_in[0];
    const float* W_enc = (const float*)d_in[1];
    const float* b_enc = (const float*)d_in[2];
    const float* W1    = (const float*)d_in[3];
    const float* b1    = (const float*)d_in[4];
    const float* W2    = (const float*)d_in[5];
    const float* b2    = (const float*)d_in[6];
    const float* pos   = (const float*)d_in[7];

    float* out   = (float*)d_out;          // (B,P,D) first
    float* xcopy = out + OUT_T_ELEMS;      // then p = x passthrough

    k_all<<<PAIRS/4, 128>>>(x, xcopy, W_enc, b_enc, pos, W1, b1, W2, b2, out);
}